// round 12
// baseline (speedup 1.0000x reference)
#include <cuda_runtime.h>
#include <cuda_bf16.h>
#include <cstdint>
#include <math.h>

#define BB 2
#define SS 2048
#define DD 1024
#define HH 16
#define HDIM 64

__device__ float g_q[BB * HH * SS * HDIM];
__device__ float g_k[BB * HH * SS * HDIM];
__device__ float g_v[BB * HH * SS * HDIM];
__device__ float g_ctx[BB * SS * DD];
// tf32-rounded copies (values are fp32 bit-patterns already rounded to tf32)
__device__ float g_xt[BB * SS * DD];
__device__ float g_wqt[DD * DD];
__device__ float g_wkt[DD * DD];
__device__ float g_wvt[DD * DD];
__device__ float g_wot[DD * DD];

__device__ __forceinline__ uint32_t f2tf(float f) {
    uint32_t u;
    asm("cvt.rna.tf32.f32 %0, %1;" : "=r"(u) : "f"(f));
    return u;
}
__device__ __forceinline__ uint32_t fau(float f) { return __float_as_uint(f); }

__device__ __forceinline__ uint32_t smem_u32(const void* p) {
    uint32_t a;
    asm("{ .reg .u64 t; cvta.to.shared.u64 t, %1; cvt.u32.u64 %0, t; }" : "=r"(a) : "l"(p));
    return a;
}
__device__ __forceinline__ void cp16(uint32_t sdst, const float* gsrc) {
    asm volatile("cp.async.ca.shared.global [%0], [%1], 16;" :: "r"(sdst), "l"(gsrc));
}
#define CP_COMMIT() asm volatile("cp.async.commit_group;" ::: "memory")
#define CP_WAIT0()  asm volatile("cp.async.wait_group 0;" ::: "memory")

// mma.sync m16n8k8 tf32, fp32 accumulate (in-place)
__device__ __forceinline__ void mma8(float* c, const uint32_t* a, const uint32_t* b) {
    asm volatile(
        "mma.sync.aligned.m16n8k8.row.col.f32.tf32.tf32.f32 "
        "{%0,%1,%2,%3},{%4,%5,%6,%7},{%8,%9},{%0,%1,%2,%3};"
        : "+f"(c[0]), "+f"(c[1]), "+f"(c[2]), "+f"(c[3])
        : "r"(a[0]), "r"(a[1]), "r"(a[2]), "r"(a[3]), "r"(b[0]), "r"(b[1]));
}

// Prepass: round a fp32 tensor to tf32 values, float4 at a time.
__global__ void __launch_bounds__(256)
tf32_round(const float* __restrict__ src, float* __restrict__ dst, int n4)
{
    int i = blockIdx.x * 256 + threadIdx.x;
    if (i < n4) {
        float4 v = ((const float4*)src)[i];
        uint4 t = make_uint4(f2tf(v.x), f2tf(v.y), f2tf(v.z), f2tf(v.w));
        ((uint4*)dst)[i] = t;
    }
}

// ---------------------------------------------------------------------------
// tf32 tensor-core GEMM body: out[4096,1024] = A @ W^T (+bias).
// A and W are PRE-ROUNDED tf32 values: fragment loads are plain LDS.
// CTA tile 128x128, K-chunk 32, 256 threads, cp.async double-buffered smem,
// one barrier per chunk, 2 CTAs/SM. reshape=1 scatters tf32-rounded q/k/v.
// ---------------------------------------------------------------------------
#define GEMM_SMEM (73728)   // 2 stages x (A 128x36 + B 128x36) floats

__device__ __forceinline__ void
gemm_body(const float* __restrict__ A, const float* __restrict__ W,
          const float* __restrict__ bias, float* __restrict__ out,
          int reshape, float* sm)
{
    const int tid = threadIdx.x;
    const int wid = tid >> 5, lane = tid & 31;
    const int g = lane >> 2, c = lane & 3;
    const int m0 = blockIdx.y << 7, n0 = blockIdx.x << 7;
    const int wm = (wid >> 2) << 6, wn = (wid & 3) << 5;

    const uint32_t su = smem_u32(sm);

    float acc[4][4][4];
#pragma unroll
    for (int i = 0; i < 4; i++)
#pragma unroll
        for (int j = 0; j < 4; j++)
#pragma unroll
            for (int e = 0; e < 4; e++) acc[i][j][e] = 0.f;

    int fr[4], fc[4];
#pragma unroll
    for (int i = 0; i < 4; i++) {
        int f = (i << 8) + tid;
        fr[i] = f >> 3;
        fc[i] = (f & 7) << 2;
    }

    // prologue: async-fill stage 0
#pragma unroll
    for (int i = 0; i < 4; i++) {
        uint32_t so = (uint32_t)(fr[i] * 36 + fc[i]) << 2;
        cp16(su + so, A + (size_t)(m0 + fr[i]) * DD + fc[i]);
        cp16(su + 18432 + so, W + (size_t)(n0 + fr[i]) * DD + fc[i]);
    }
    CP_COMMIT();

    for (int kk = 0; kk < 32; kk++) {
        CP_WAIT0();
        __syncthreads();

        if (kk < 31) {
            const int k0n = (kk + 1) << 5;
            const uint32_t sb = su + ((kk + 1) & 1) * 36864;
#pragma unroll
            for (int i = 0; i < 4; i++) {
                uint32_t so = (uint32_t)(fr[i] * 36 + fc[i]) << 2;
                cp16(sb + so, A + (size_t)(m0 + fr[i]) * DD + k0n + fc[i]);
                cp16(sb + 18432 + so, W + (size_t)(n0 + fr[i]) * DD + k0n + fc[i]);
            }
            CP_COMMIT();
        }

        const float* As_ = sm + (kk & 1) * 9216;
        const float* Bs_ = As_ + 4608;

#pragma unroll
        for (int s = 0; s < 4; s++) {
            const int k0 = s << 3;
            uint32_t af[4][4];
#pragma unroll
            for (int i = 0; i < 4; i++) {
                const float* q = As_ + (wm + (i << 4) + g) * 36 + k0 + c;
                af[i][0] = fau(q[0]);
                af[i][2] = fau(q[4]);
                af[i][1] = fau(q[8 * 36]);
                af[i][3] = fau(q[8 * 36 + 4]);
            }
#pragma unroll
            for (int j = 0; j < 4; j++) {
                const float* r = Bs_ + (wn + (j << 3) + g) * 36 + k0 + c;
                uint32_t bf[2] = {fau(r[0]), fau(r[4])};
#pragma unroll
                for (int i = 0; i < 4; i++) mma8(acc[i][j], af[i], bf);
            }
        }
    }

    // epilogue
#pragma unroll
    for (int i = 0; i < 4; i++) {
        int r0 = m0 + wm + (i << 4) + g;
        int r1 = r0 + 8;
#pragma unroll
        for (int j = 0; j < 4; j++) {
            int cb = n0 + wn + (j << 3) + (c << 1);
            if (reshape) {
                // write tf32-rounded q/k/v (consumed as mma operands downstream)
                int h = cb >> 6, d = cb & 63;
                int b0r = r0 >> 11, s0r = r0 & 2047;
                int b1r = r1 >> 11, s1r = r1 & 2047;
                *(uint2*)(out + ((size_t)((b0r * HH + h) * SS + s0r)) * HDIM + d) =
                    make_uint2(f2tf(acc[i][j][0]), f2tf(acc[i][j][1]));
                *(uint2*)(out + ((size_t)((b1r * HH + h) * SS + s1r)) * HDIM + d) =
                    make_uint2(f2tf(acc[i][j][2]), f2tf(acc[i][j][3]));
            } else {
                float bb0 = bias ? bias[cb] : 0.f;
                float bb1 = bias ? bias[cb + 1] : 0.f;
                *(float2*)(out + (size_t)r0 * DD + cb) =
                    make_float2(acc[i][j][0] + bb0, acc[i][j][1] + bb1);
                *(float2*)(out + (size_t)r1 * DD + cb) =
                    make_float2(acc[i][j][2] + bb0, acc[i][j][3] + bb1);
            }
        }
    }
}

// Fused Q/K/V projection: blockIdx.z selects weight + destination.
__global__ void __launch_bounds__(256, 2)
qkv_gemm(const float* __restrict__ x,
         const float* __restrict__ Wq, const float* __restrict__ Wk,
         const float* __restrict__ Wv,
         float* __restrict__ q, float* __restrict__ k, float* __restrict__ v)
{
    extern __shared__ float sm[];
    const float* W = (blockIdx.z == 0) ? Wq : (blockIdx.z == 1) ? Wk : Wv;
    float* out = (blockIdx.z == 0) ? q : (blockIdx.z == 1) ? k : v;
    gemm_body(x, W, nullptr, out, 1, sm);
}

// Output projection.
__global__ void __launch_bounds__(256, 2)
oproj_gemm(const float* __restrict__ A, const float* __restrict__ W,
           const float* __restrict__ bias, float* __restrict__ out)
{
    extern __shared__ float sm[];
    gemm_body(A, W, bias, out, 0, sm);
}

// ---------------------------------------------------------------------------
// Causal flash attention on tf32 mma. 128 threads (4 warps), q-tile 64,
// k-tile 64. Q/K/V are pre-rounded tf32: fills are raw cp.async, fragment
// loads plain LDS. P relayed via intra-quad shuffles (no smem).
// smem: Q 64x68 + K 64x68 + V 64x72 = 52 KB -> 4 CTAs/SM.
// ---------------------------------------------------------------------------
#define ATTN_SMEM (53248)   // floats: Q 4352 + K 4352 + V 4608

__global__ void __launch_bounds__(128)
attn_kernel(float* __restrict__ ctx)
{
    extern __shared__ float sm[];
    float* smQ = sm;            // 64 x 68
    float* smK = sm + 4352;     // 64 x 68
    float* smV = sm + 8704;     // 64 x 72
    const uint32_t suQ = smem_u32(smQ);
    const uint32_t suK = smem_u32(smK);
    const uint32_t suV = smem_u32(smV);

    const int tid = threadIdx.x;
    const int wid = tid >> 5, lane = tid & 31;
    const int g = lane >> 2, c = lane & 3;
    const int mb = wid << 4;
    const int bh = blockIdx.y;
    const int q0 = blockIdx.x << 6;

    const float* Qb = g_q + (size_t)bh * SS * HDIM;
    const float* Kb = g_k + (size_t)bh * SS * HDIM;
    const float* Vb = g_v + (size_t)bh * SS * HDIM;

    // Q fill via cp.async (pre-rounded tf32)
#pragma unroll
    for (int i = 0; i < 8; i++) {
        int f = (i << 7) + tid;
        int r = f >> 4, c4 = (f & 15) << 2;
        cp16(suQ + ((uint32_t)(r * 68 + c4) << 2), Qb + (size_t)(q0 + r) * HDIM + c4);
    }
    CP_COMMIT();

    float o[8][4];
#pragma unroll
    for (int j = 0; j < 8; j++)
#pragma unroll
        for (int e = 0; e < 4; e++) o[j][e] = 0.f;
    float m0i = -1e30f, m1i = -1e30f, l0 = 0.f, l1 = 0.f;

    const int row0 = q0 + mb + g;
    const int row1 = row0 + 8;
    const int ktiles = (q0 >> 6) + 1;
    const int src1 = (lane & ~3) | (c >> 1);
    const int src2 = src1 | 2;
    const bool odd = (c & 1);

    for (int kt = 0; kt < ktiles; kt++) {
        const int kvb = kt << 6;
        __syncthreads();   // previous tile's reads complete before overwrite
        // K, V fill via cp.async
#pragma unroll
        for (int i = 0; i < 8; i++) {
            int f = (i << 7) + tid;
            int r = f >> 4, c4 = (f & 15) << 2;
            cp16(suK + ((uint32_t)(r * 68 + c4) << 2), Kb + (size_t)(kvb + r) * HDIM + c4);
            cp16(suV + ((uint32_t)(r * 72 + c4) << 2), Vb + (size_t)(kvb + r) * HDIM + c4);
        }
        CP_COMMIT();
        CP_WAIT0();
        __syncthreads();

        // S = Q K^T
        float s[8][4];
#pragma unroll
        for (int j = 0; j < 8; j++)
#pragma unroll
            for (int e = 0; e < 4; e++) s[j][e] = 0.f;
#pragma unroll
        for (int k0 = 0; k0 < 64; k0 += 8) {
            uint32_t a[4];
            const float* q = smQ + (mb + g) * 68 + k0 + c;
            a[0] = fau(q[0]);
            a[2] = fau(q[4]);
            a[1] = fau(q[8 * 68]);
            a[3] = fau(q[8 * 68 + 4]);
#pragma unroll
            for (int j = 0; j < 8; j++) {
                const float* r = smK + ((j << 3) + g) * 68 + k0 + c;
                uint32_t b[2] = {fau(r[0]), fau(r[4])};
                mma8(s[j], a, b);
            }
        }

        // scale + causal mask
        const bool diag = (kt == ktiles - 1);
#pragma unroll
        for (int j = 0; j < 8; j++) {
            int cg = kvb + (j << 3) + (c << 1);
            s[j][0] *= 0.125f; s[j][1] *= 0.125f;
            s[j][2] *= 0.125f; s[j][3] *= 0.125f;
            if (diag) {
                if (cg > row0)     s[j][0] = -1e30f;
                if (cg + 1 > row0) s[j][1] = -1e30f;
                if (cg > row1)     s[j][2] = -1e30f;
                if (cg + 1 > row1) s[j][3] = -1e30f;
            }
        }

        // row max (quad-local)
        float mx0 = -1e30f, mx1 = -1e30f;
#pragma unroll
        for (int j = 0; j < 8; j++) {
            mx0 = fmaxf(mx0, fmaxf(s[j][0], s[j][1]));
            mx1 = fmaxf(mx1, fmaxf(s[j][2], s[j][3]));
        }
        mx0 = fmaxf(mx0, __shfl_xor_sync(0xffffffffu, mx0, 1));
        mx0 = fmaxf(mx0, __shfl_xor_sync(0xffffffffu, mx0, 2));
        mx1 = fmaxf(mx1, __shfl_xor_sync(0xffffffffu, mx1, 1));
        mx1 = fmaxf(mx1, __shfl_xor_sync(0xffffffffu, mx1, 2));

        float mn0 = fmaxf(m0i, mx0), mn1 = fmaxf(m1i, mx1);
        float al0 = __expf(m0i - mn0), al1 = __expf(m1i - mn1);
        m0i = mn0; m1i = mn1;

        float sum0 = 0.f, sum1 = 0.f;
#pragma unroll
        for (int j = 0; j < 8; j++) {
            s[j][0] = __expf(s[j][0] - mn0);
            s[j][1] = __expf(s[j][1] - mn0);
            s[j][2] = __expf(s[j][2] - mn1);
            s[j][3] = __expf(s[j][3] - mn1);
            sum0 += s[j][0] + s[j][1];
            sum1 += s[j][2] + s[j][3];
        }
        sum0 += __shfl_xor_sync(0xffffffffu, sum0, 1);
        sum0 += __shfl_xor_sync(0xffffffffu, sum0, 2);
        sum1 += __shfl_xor_sync(0xffffffffu, sum1, 1);
        sum1 += __shfl_xor_sync(0xffffffffu, sum1, 2);
        l0 = l0 * al0 + sum0;
        l1 = l1 * al1 + sum1;

#pragma unroll
        for (int j = 0; j < 8; j++) {
            o[j][0] *= al0; o[j][1] *= al0;
            o[j][2] *= al1; o[j][3] *= al1;
        }

        // tf32-round P in registers
#pragma unroll
        for (int j = 0; j < 8; j++)
#pragma unroll
            for (int e = 0; e < 4; e++)
                s[j][e] = __uint_as_float(f2tf(s[j][e]));

        // O += P V  (A-fragments assembled via intra-quad shuffles)
#pragma unroll
        for (int j = 0; j < 8; j++) {
            float e00 = __shfl_sync(0xffffffffu, s[j][0], src1);
            float e01 = __shfl_sync(0xffffffffu, s[j][1], src1);
            float e10 = __shfl_sync(0xffffffffu, s[j][2], src1);
            float e11 = __shfl_sync(0xffffffffu, s[j][3], src1);
            float f00 = __shfl_sync(0xffffffffu, s[j][0], src2);
            float f01 = __shfl_sync(0xffffffffu, s[j][1], src2);
            float f10 = __shfl_sync(0xffffffffu, s[j][2], src2);
            float f11 = __shfl_sync(0xffffffffu, s[j][3], src2);
            uint32_t a[4];
            a[0] = fau(odd ? e01 : e00);
            a[1] = fau(odd ? e11 : e10);
            a[2] = fau(odd ? f01 : f00);
            a[3] = fau(odd ? f11 : f10);
            const float* vbase = smV + ((j << 3) + c) * 72 + g;
#pragma unroll
            for (int d = 0; d < 8; d++) {
                uint32_t b[2] = {fau(vbase[d << 3]), fau(vbase[(d << 3) + 4 * 72])};
                mma8(o[d], a, b);
            }
        }
    }

    // epilogue: write ctx tf32-rounded (oproj consumes it as mma operand)
    const int b = bh >> 4, h = bh & 15;
    float inv0 = 1.0f / l0, inv1 = 1.0f / l1;
    float* out0 = ctx + ((size_t)(b * SS + row0)) * DD + (h << 6) + (c << 1);
    float* out1 = ctx + ((size_t)(b * SS + row1)) * DD + (h << 6) + (c << 1);
#pragma unroll
    for (int j = 0; j < 8; j++) {
        *(uint2*)(out0 + (j << 3)) = make_uint2(f2tf(o[j][0] * inv0), f2tf(o[j][1] * inv0));
        *(uint2*)(out1 + (j << 3)) = make_uint2(f2tf(o[j][2] * inv1), f2tf(o[j][3] * inv1));
    }
}

// ---------------------------------------------------------------------------
extern "C" void kernel_launch(void* const* d_in, const int* in_sizes, int n_in,
                              void* d_out, int out_size)
{
    const float* x  = (const float*)d_in[0];
    const float* Wq = (const float*)d_in[1];
    const float* Wk = (const float*)d_in[2];
    const float* Wv = (const float*)d_in[3];
    const float* Wo = (const float*)d_in[4];
    const float* bo = (const float*)d_in[5];
    float* out = (float*)d_out;

    float *q_p, *k_p, *v_p, *c_p, *xt, *wqt, *wkt, *wvt, *wot;
    cudaGetSymbolAddress((void**)&q_p, g_q);
    cudaGetSymbolAddress((void**)&k_p, g_k);
    cudaGetSymbolAddress((void**)&v_p, g_v);
    cudaGetSymbolAddress((void**)&c_p, g_ctx);
    cudaGetSymbolAddress((void**)&xt,  g_xt);
    cudaGetSymbolAddress((void**)&wqt, g_wqt);
    cudaGetSymbolAddress((void**)&wkt, g_wkt);
    cudaGetSymbolAddress((void**)&wvt, g_wvt);
    cudaGetSymbolAddress((void**)&wot, g_wot);

    cudaFuncSetAttribute(qkv_gemm, cudaFuncAttributeMaxDynamicSharedMemorySize, GEMM_SMEM);
    cudaFuncSetAttribute(oproj_gemm, cudaFuncAttributeMaxDynamicSharedMemorySize, GEMM_SMEM);
    cudaFuncSetAttribute(attn_kernel, cudaFuncAttributeMaxDynamicSharedMemorySize, ATTN_SMEM);

    const int nx4 = BB * SS * DD / 4;      // 1,048,576 float4s
    const int nw4 = DD * DD / 4;           //   262,144 float4s
    tf32_round<<<(nx4 + 255) / 256, 256>>>(x,  xt,  nx4);
    tf32_round<<<(nw4 + 255) / 256, 256>>>(Wq, wqt, nw4);
    tf32_round<<<(nw4 + 255) / 256, 256>>>(Wk, wkt, nw4);
    tf32_round<<<(nw4 + 255) / 256, 256>>>(Wv, wvt, nw4);
    tf32_round<<<(nw4 + 255) / 256, 256>>>(Wo, wot, nw4);

    qkv_gemm<<<dim3(8, 32, 3), 256, GEMM_SMEM>>>(xt, wqt, wkt, wvt, q_p, k_p, v_p);

    attn_kernel<<<dim3(32, 32), 128, ATTN_SMEM>>>(c_p);

    oproj_gemm<<<dim3(8, 32), 256, GEMM_SMEM>>>(c_p, wot, bo, out);
}

// round 14
// speedup vs baseline: 1.5090x; 1.5090x over previous
#include <cuda_runtime.h>
#include <cuda_bf16.h>
#include <cstdint>
#include <math.h>

#define BB 2
#define SS 2048
#define DD 1024
#define HH 16
#define HDIM 64

__device__ float g_q[BB * HH * SS * HDIM];
__device__ float g_k[BB * HH * SS * HDIM];
__device__ float g_v[BB * HH * SS * HDIM];
__device__ float g_ctx[BB * SS * DD];

// fp32 -> tf32 (round to nearest) kept in a b32 register / stored as float bits
__device__ __forceinline__ uint32_t f2tf(float f) {
    uint32_t u;
    asm("cvt.rna.tf32.f32 %0, %1;" : "=r"(u) : "f"(f));
    return u;
}
__device__ __forceinline__ uint32_t fau(float f) { return __float_as_uint(f); }

__device__ __forceinline__ uint32_t smem_u32(const void* p) {
    uint32_t a;
    asm("{ .reg .u64 t; cvta.to.shared.u64 t, %1; cvt.u32.u64 %0, t; }" : "=r"(a) : "l"(p));
    return a;
}
__device__ __forceinline__ void cp16(uint32_t sdst, const float* gsrc) {
    asm volatile("cp.async.ca.shared.global [%0], [%1], 16;" :: "r"(sdst), "l"(gsrc));
}
#define CP_COMMIT() asm volatile("cp.async.commit_group;" ::: "memory")
#define CP_WAIT0()  asm volatile("cp.async.wait_group 0;" ::: "memory")

// mma.sync m16n8k8 tf32, fp32 accumulate (in-place)
__device__ __forceinline__ void mma8(float* c, const uint32_t* a, const uint32_t* b) {
    asm volatile(
        "mma.sync.aligned.m16n8k8.row.col.f32.tf32.tf32.f32 "
        "{%0,%1,%2,%3},{%4,%5,%6,%7},{%8,%9},{%0,%1,%2,%3};"
        : "+f"(c[0]), "+f"(c[1]), "+f"(c[2]), "+f"(c[3])
        : "r"(a[0]), "r"(a[1]), "r"(a[2]), "r"(a[3]), "r"(b[0]), "r"(b[1]));
}

__device__ __forceinline__ void st_tf4(float* dst, float4 v) {
    uint4 t = make_uint4(f2tf(v.x), f2tf(v.y), f2tf(v.z), f2tf(v.w));
    *(uint4*)dst = t;
}

// ---------------------------------------------------------------------------
// tf32 tensor-core GEMM body: out[4096,1024] = A @ W^T (+bias).
// CTA tile 128x128, K-chunk 32, 256 threads (8 warps, 64x32 each).
// cp.async double-buffered smem (raw fp32; tf32 cvt at fragment load),
// ONE barrier per K-chunk, 2 CTAs/SM via launch_bounds reg cap.
// reshape=1 scatters to [B,H,S,64].
// ---------------------------------------------------------------------------
#define GEMM_SMEM (73728)   // 2 stages x (A 128x36 + B 128x36) floats

__device__ __forceinline__ void
gemm_body(const float* __restrict__ A, const float* __restrict__ W,
          const float* __restrict__ bias, float* __restrict__ out,
          int reshape, float* sm)
{
    const int tid = threadIdx.x;
    const int wid = tid >> 5, lane = tid & 31;
    const int g = lane >> 2, c = lane & 3;
    const int m0 = blockIdx.y << 7, n0 = blockIdx.x << 7;
    const int wm = (wid >> 2) << 6, wn = (wid & 3) << 5;

    const uint32_t su = smem_u32(sm);

    float acc[4][4][4];
#pragma unroll
    for (int i = 0; i < 4; i++)
#pragma unroll
        for (int j = 0; j < 4; j++)
#pragma unroll
            for (int e = 0; e < 4; e++) acc[i][j][e] = 0.f;

    int fr[4], fc[4];
#pragma unroll
    for (int i = 0; i < 4; i++) {
        int f = (i << 8) + tid;
        fr[i] = f >> 3;
        fc[i] = (f & 7) << 2;
    }

    // prologue: async-fill stage 0
#pragma unroll
    for (int i = 0; i < 4; i++) {
        uint32_t so = (uint32_t)(fr[i] * 36 + fc[i]) << 2;
        cp16(su + so, A + (size_t)(m0 + fr[i]) * DD + fc[i]);
        cp16(su + 18432 + so, W + (size_t)(n0 + fr[i]) * DD + fc[i]);
    }
    CP_COMMIT();

    for (int kk = 0; kk < 32; kk++) {
        CP_WAIT0();
        __syncthreads();

        if (kk < 31) {
            const int k0n = (kk + 1) << 5;
            const uint32_t sb = su + ((kk + 1) & 1) * 36864;
#pragma unroll
            for (int i = 0; i < 4; i++) {
                uint32_t so = (uint32_t)(fr[i] * 36 + fc[i]) << 2;
                cp16(sb + so, A + (size_t)(m0 + fr[i]) * DD + k0n + fc[i]);
                cp16(sb + 18432 + so, W + (size_t)(n0 + fr[i]) * DD + k0n + fc[i]);
            }
            CP_COMMIT();
        }

        const float* As_ = sm + (kk & 1) * 9216;
        const float* Bs_ = As_ + 4608;

#pragma unroll
        for (int s = 0; s < 4; s++) {
            const int k0 = s << 3;
            uint32_t af[4][4];
#pragma unroll
            for (int i = 0; i < 4; i++) {
                const float* q = As_ + (wm + (i << 4) + g) * 36 + k0 + c;
                af[i][0] = f2tf(q[0]);
                af[i][2] = f2tf(q[4]);
                af[i][1] = f2tf(q[8 * 36]);
                af[i][3] = f2tf(q[8 * 36 + 4]);
            }
#pragma unroll
            for (int j = 0; j < 4; j++) {
                const float* r = Bs_ + (wn + (j << 3) + g) * 36 + k0 + c;
                uint32_t bf[2] = {f2tf(r[0]), f2tf(r[4])};
#pragma unroll
                for (int i = 0; i < 4; i++) mma8(acc[i][j], af[i], bf);
            }
        }
    }

    // epilogue: direct float2 stores from fragments
#pragma unroll
    for (int i = 0; i < 4; i++) {
        int r0 = m0 + wm + (i << 4) + g;
        int r1 = r0 + 8;
#pragma unroll
        for (int j = 0; j < 4; j++) {
            int cb = n0 + wn + (j << 3) + (c << 1);
            if (reshape) {
                int h = cb >> 6, d = cb & 63;
                int b0r = r0 >> 11, s0r = r0 & 2047;
                int b1r = r1 >> 11, s1r = r1 & 2047;
                *(float2*)(out + ((size_t)((b0r * HH + h) * SS + s0r)) * HDIM + d) =
                    make_float2(acc[i][j][0], acc[i][j][1]);
                *(float2*)(out + ((size_t)((b1r * HH + h) * SS + s1r)) * HDIM + d) =
                    make_float2(acc[i][j][2], acc[i][j][3]);
            } else {
                float bb0 = bias ? bias[cb] : 0.f;
                float bb1 = bias ? bias[cb + 1] : 0.f;
                *(float2*)(out + (size_t)r0 * DD + cb) =
                    make_float2(acc[i][j][0] + bb0, acc[i][j][1] + bb1);
                *(float2*)(out + (size_t)r1 * DD + cb) =
                    make_float2(acc[i][j][2] + bb0, acc[i][j][3] + bb1);
            }
        }
    }
}

// Fused Q/K/V projection: blockIdx.z selects weight + destination.
__global__ void __launch_bounds__(256, 2)
qkv_gemm(const float* __restrict__ x,
         const float* __restrict__ Wq, const float* __restrict__ Wk,
         const float* __restrict__ Wv,
         float* __restrict__ q, float* __restrict__ k, float* __restrict__ v)
{
    extern __shared__ float sm[];
    const float* W = (blockIdx.z == 0) ? Wq : (blockIdx.z == 1) ? Wk : Wv;
    float* out = (blockIdx.z == 0) ? q : (blockIdx.z == 1) ? k : v;
    gemm_body(x, W, nullptr, out, 1, sm);
}

// Output projection.
__global__ void __launch_bounds__(256, 2)
oproj_gemm(const float* __restrict__ A, const float* __restrict__ W,
           const float* __restrict__ bias, float* __restrict__ out)
{
    extern __shared__ float sm[];
    gemm_body(A, W, bias, out, 0, sm);
}

// ---------------------------------------------------------------------------
// Causal flash attention on tf32 mma. 128 threads (4 warps), q-tile 64,
// k-tile 64. Warp w owns rows [16w,16w+16): softmax stats are quad-local.
// P never touches smem: the S accumulator (C-layout, cols 2c/2c+1) is
// converted to the PV A-fragment (cols c/c+4) with intra-quad shuffles.
// Q-tiles issued heaviest-first (reversed blockIdx.x) for tail balance.
// smem: Q 64x68 + K 64x68 + V 64x72 = 52 KB -> 4 CTAs/SM.
// ---------------------------------------------------------------------------
#define ATTN_SMEM (53248)   // floats: Q 4352 + K 4352 + V 4608

__global__ void __launch_bounds__(128)
attn_kernel(float* __restrict__ ctx)
{
    extern __shared__ float sm[];
    float* smQ = sm;            // 64 x 68
    float* smK = sm + 4352;     // 64 x 68
    float* smV = sm + 8704;     // 64 x 72

    const int tid = threadIdx.x;
    const int wid = tid >> 5, lane = tid & 31;
    const int g = lane >> 2, c = lane & 3;
    const int mb = wid << 4;
    const int bh = blockIdx.y;
    const int q0 = (31 - blockIdx.x) << 6;   // heaviest q-tiles first

    const float* Qb = g_q + (size_t)bh * SS * HDIM;
    const float* Kb = g_k + (size_t)bh * SS * HDIM;
    const float* Vb = g_v + (size_t)bh * SS * HDIM;

    // Q fill (tf32)
#pragma unroll
    for (int i = 0; i < 8; i++) {
        int f = (i << 7) + tid;
        int r = f >> 4, c4 = (f & 15) << 2;
        float4 v = *(const float4*)(Qb + (size_t)(q0 + r) * HDIM + c4);
        st_tf4(smQ + r * 68 + c4, v);
    }

    float o[8][4];
#pragma unroll
    for (int j = 0; j < 8; j++)
#pragma unroll
        for (int e = 0; e < 4; e++) o[j][e] = 0.f;
    float m0i = -1e30f, m1i = -1e30f, l0 = 0.f, l1 = 0.f;

    const int row0 = q0 + mb + g;
    const int row1 = row0 + 8;
    const int ktiles = (q0 >> 6) + 1;
    const int src1 = (lane & ~3) | (c >> 1);   // quad-lane holding col c
    const int src2 = src1 | 2;                 // quad-lane holding col c+4
    const bool odd = (c & 1);

    for (int kt = 0; kt < ktiles; kt++) {
        const int kvb = kt << 6;
        __syncthreads();
        // K, V fill (tf32)
#pragma unroll
        for (int i = 0; i < 8; i++) {
            int f = (i << 7) + tid;
            int r = f >> 4, c4 = (f & 15) << 2;
            float4 kv = *(const float4*)(Kb + (size_t)(kvb + r) * HDIM + c4);
            st_tf4(smK + r * 68 + c4, kv);
            float4 vv = *(const float4*)(Vb + (size_t)(kvb + r) * HDIM + c4);
            st_tf4(smV + r * 72 + c4, vv);
        }
        __syncthreads();

        // S = Q K^T
        float s[8][4];
#pragma unroll
        for (int j = 0; j < 8; j++)
#pragma unroll
            for (int e = 0; e < 4; e++) s[j][e] = 0.f;
#pragma unroll
        for (int k0 = 0; k0 < 64; k0 += 8) {
            uint32_t a[4];
            const float* q = smQ + (mb + g) * 68 + k0 + c;
            a[0] = fau(q[0]);
            a[2] = fau(q[4]);
            a[1] = fau(q[8 * 68]);
            a[3] = fau(q[8 * 68 + 4]);
#pragma unroll
            for (int j = 0; j < 8; j++) {
                const float* r = smK + ((j << 3) + g) * 68 + k0 + c;
                uint32_t b[2] = {fau(r[0]), fau(r[4])};
                mma8(s[j], a, b);
            }
        }

        // scale + causal mask
        const bool diag = (kt == ktiles - 1);
#pragma unroll
        for (int j = 0; j < 8; j++) {
            int cg = kvb + (j << 3) + (c << 1);
            s[j][0] *= 0.125f; s[j][1] *= 0.125f;
            s[j][2] *= 0.125f; s[j][3] *= 0.125f;
            if (diag) {
                if (cg > row0)     s[j][0] = -1e30f;
                if (cg + 1 > row0) s[j][1] = -1e30f;
                if (cg > row1)     s[j][2] = -1e30f;
                if (cg + 1 > row1) s[j][3] = -1e30f;
            }
        }

        // row max (quad-local)
        float mx0 = -1e30f, mx1 = -1e30f;
#pragma unroll
        for (int j = 0; j < 8; j++) {
            mx0 = fmaxf(mx0, fmaxf(s[j][0], s[j][1]));
            mx1 = fmaxf(mx1, fmaxf(s[j][2], s[j][3]));
        }
        mx0 = fmaxf(mx0, __shfl_xor_sync(0xffffffffu, mx0, 1));
        mx0 = fmaxf(mx0, __shfl_xor_sync(0xffffffffu, mx0, 2));
        mx1 = fmaxf(mx1, __shfl_xor_sync(0xffffffffu, mx1, 1));
        mx1 = fmaxf(mx1, __shfl_xor_sync(0xffffffffu, mx1, 2));

        float mn0 = fmaxf(m0i, mx0), mn1 = fmaxf(m1i, mx1);
        float al0 = __expf(m0i - mn0), al1 = __expf(m1i - mn1);
        m0i = mn0; m1i = mn1;

        float sum0 = 0.f, sum1 = 0.f;
#pragma unroll
        for (int j = 0; j < 8; j++) {
            s[j][0] = __expf(s[j][0] - mn0);
            s[j][1] = __expf(s[j][1] - mn0);
            s[j][2] = __expf(s[j][2] - mn1);
            s[j][3] = __expf(s[j][3] - mn1);
            sum0 += s[j][0] + s[j][1];
            sum1 += s[j][2] + s[j][3];
        }
        sum0 += __shfl_xor_sync(0xffffffffu, sum0, 1);
        sum0 += __shfl_xor_sync(0xffffffffu, sum0, 2);
        sum1 += __shfl_xor_sync(0xffffffffu, sum1, 1);
        sum1 += __shfl_xor_sync(0xffffffffu, sum1, 2);
        l0 = l0 * al0 + sum0;
        l1 = l1 * al1 + sum1;

#pragma unroll
        for (int j = 0; j < 8; j++) {
            o[j][0] *= al0; o[j][1] *= al0;
            o[j][2] *= al1; o[j][3] *= al1;
        }

        // tf32-round P in registers
#pragma unroll
        for (int j = 0; j < 8; j++)
#pragma unroll
            for (int e = 0; e < 4; e++)
                s[j][e] = __uint_as_float(f2tf(s[j][e]));

        // O += P V  (A-fragments assembled via intra-quad shuffles)
#pragma unroll
        for (int j = 0; j < 8; j++) {
            float e00 = __shfl_sync(0xffffffffu, s[j][0], src1);
            float e01 = __shfl_sync(0xffffffffu, s[j][1], src1);
            float e10 = __shfl_sync(0xffffffffu, s[j][2], src1);
            float e11 = __shfl_sync(0xffffffffu, s[j][3], src1);
            float f00 = __shfl_sync(0xffffffffu, s[j][0], src2);
            float f01 = __shfl_sync(0xffffffffu, s[j][1], src2);
            float f10 = __shfl_sync(0xffffffffu, s[j][2], src2);
            float f11 = __shfl_sync(0xffffffffu, s[j][3], src2);
            uint32_t a[4];
            a[0] = fau(odd ? e01 : e00);   // P[g][8j+c]
            a[1] = fau(odd ? e11 : e10);   // P[g+8][8j+c]
            a[2] = fau(odd ? f01 : f00);   // P[g][8j+c+4]
            a[3] = fau(odd ? f11 : f10);   // P[g+8][8j+c+4]
            const float* vbase = smV + ((j << 3) + c) * 72 + g;
#pragma unroll
            for (int d = 0; d < 8; d++) {
                uint32_t b[2] = {fau(vbase[d << 3]), fau(vbase[(d << 3) + 4 * 72])};
                mma8(o[d], a, b);
            }
        }
    }

    // epilogue
    const int b = bh >> 4, h = bh & 15;
    float inv0 = 1.0f / l0, inv1 = 1.0f / l1;
    float* out0 = ctx + ((size_t)(b * SS + row0)) * DD + (h << 6) + (c << 1);
    float* out1 = ctx + ((size_t)(b * SS + row1)) * DD + (h << 6) + (c << 1);
#pragma unroll
    for (int j = 0; j < 8; j++) {
        *(float2*)(out0 + (j << 3)) = make_float2(o[j][0] * inv0, o[j][1] * inv0);
        *(float2*)(out1 + (j << 3)) = make_float2(o[j][2] * inv1, o[j][3] * inv1);
    }
}

// ---------------------------------------------------------------------------
extern "C" void kernel_launch(void* const* d_in, const int* in_sizes, int n_in,
                              void* d_out, int out_size)
{
    const float* x  = (const float*)d_in[0];
    const float* Wq = (const float*)d_in[1];
    const float* Wk = (const float*)d_in[2];
    const float* Wv = (const float*)d_in[3];
    const float* Wo = (const float*)d_in[4];
    const float* bo = (const float*)d_in[5];
    float* out = (float*)d_out;

    float *q_p, *k_p, *v_p, *c_p;
    cudaGetSymbolAddress((void**)&q_p, g_q);
    cudaGetSymbolAddress((void**)&k_p, g_k);
    cudaGetSymbolAddress((void**)&v_p, g_v);
    cudaGetSymbolAddress((void**)&c_p, g_ctx);

    cudaFuncSetAttribute(qkv_gemm, cudaFuncAttributeMaxDynamicSharedMemorySize, GEMM_SMEM);
    cudaFuncSetAttribute(oproj_gemm, cudaFuncAttributeMaxDynamicSharedMemorySize, GEMM_SMEM);
    cudaFuncSetAttribute(attn_kernel, cudaFuncAttributeMaxDynamicSharedMemorySize, ATTN_SMEM);

    qkv_gemm<<<dim3(8, 32, 3), 256, GEMM_SMEM>>>(x, Wq, Wk, Wv, q_p, k_p, v_p);

    attn_kernel<<<dim3(32, 32), 128, ATTN_SMEM>>>(c_p);

    oproj_gemm<<<dim3(8, 32), 256, GEMM_SMEM>>>(c_p, Wo, bo, out);
}